// round 1
// baseline (speedup 1.0000x reference)
#include <cuda_runtime.h>
#include <math.h>

#define P_N 256
#define L_N 64
#define I_DIM 512
#define H_DIM 1024
#define G4 4096
#define ROWS (P_N * L_N)  // 16384

// ---- scratch (__device__ globals: allocation-free rule) ----
__device__ float g_xW[(size_t)ROWS * G4];       // precomputed x@W_ih^T + b  (268 MB)
__device__ float g_h[2][P_N * H_DIM];           // double-buffered hidden
__device__ float g_c[P_N * H_DIM];              // cell state
__device__ float g_final[P_N * H_DIM];          // h at t = length-1
__device__ float g_v[P_N * H_DIM];              // v-projection
__device__ float g_attn[P_N * H_DIM];           // out-projection
__device__ float g_pooled[H_DIM];               // column max

__device__ __forceinline__ float sigm(float x) { return 1.0f / (1.0f + expf(-x)); }

// ---- zero h0 / c0 (graph replays must be deterministic) ----
__global__ void zero_hc() {
    int i = blockIdx.x * blockDim.x + threadIdx.x;
    if (i < P_N * H_DIM) { g_h[0][i] = 0.0f; g_c[i] = 0.0f; }
}

// ---- GEMM 1: xW[row=(p*64+t)][4096] = emb[paths[row]] @ W_ih^T + (b_ih+b_hh) ----
// 64x64 tile, K=512, 256 threads, 4x4 microtile
__global__ void __launch_bounds__(256) gemm_embed(
    const int* __restrict__ paths, const float* __restrict__ emb,
    const float* __restrict__ W_ih, const float* __restrict__ b_ih,
    const float* __restrict__ b_hh)
{
    __shared__ __align__(16) float As[32 * 68];
    __shared__ __align__(16) float Bs[32 * 68];
    __shared__ int toks[64];

    const int tid = threadIdx.x;
    const int m0 = blockIdx.y * 64;
    const int n0 = blockIdx.x * 64;
    if (tid < 64) toks[tid] = paths[m0 + tid];
    __syncthreads();

    const int ty = tid >> 4;        // 0..15 -> m micro-row base ty*4
    const int tx = tid & 15;        // 0..15 -> n micro-col base tx*4
    const int lr = tid >> 3;        // 0..31  loader row
    const int lc4 = (tid & 7) * 4;  // 0..28  loader k offset

    float acc[4][4] = {};

    for (int k0 = 0; k0 < I_DIM; k0 += 32) {
        #pragma unroll
        for (int h = 0; h < 2; h++) {
            const int r = lr + h * 32;
            const float4 a = *(const float4*)(emb + (size_t)toks[r] * I_DIM + k0 + lc4);
            As[(lc4 + 0) * 68 + r] = a.x;
            As[(lc4 + 1) * 68 + r] = a.y;
            As[(lc4 + 2) * 68 + r] = a.z;
            As[(lc4 + 3) * 68 + r] = a.w;
            const float4 b = *(const float4*)(W_ih + (size_t)(n0 + r) * I_DIM + k0 + lc4);
            Bs[(lc4 + 0) * 68 + r] = b.x;
            Bs[(lc4 + 1) * 68 + r] = b.y;
            Bs[(lc4 + 2) * 68 + r] = b.z;
            Bs[(lc4 + 3) * 68 + r] = b.w;
        }
        __syncthreads();
        #pragma unroll
        for (int k = 0; k < 32; k++) {
            const float4 a = *(const float4*)&As[k * 68 + ty * 4];
            const float4 b = *(const float4*)&Bs[k * 68 + tx * 4];
            const float av[4] = {a.x, a.y, a.z, a.w};
            const float bv[4] = {b.x, b.y, b.z, b.w};
            #pragma unroll
            for (int i = 0; i < 4; i++)
                #pragma unroll
                for (int j = 0; j < 4; j++)
                    acc[i][j] += av[i] * bv[j];
        }
        __syncthreads();
    }

    #pragma unroll
    for (int i = 0; i < 4; i++) {
        const int row = m0 + ty * 4 + i;
        #pragma unroll
        for (int j = 0; j < 4; j++) {
            const int col = n0 + tx * 4 + j;
            g_xW[(size_t)row * G4 + col] = acc[i][j] + b_ih[col] + b_hh[col];
        }
    }
}

// ---- LSTM step t: gates = xW[t] + h_prev @ W_hh^T, then elementwise update ----
// Block tile: 32 paths x (4 gates x 32 h-cols). Each thread owns 4 paths x 1 h-col,
// all 4 gates -> LSTM update fully in registers.
__global__ void __launch_bounds__(256) lstm_step(
    const float* __restrict__ W_hh, const int* __restrict__ lengths, const int step)
{
    __shared__ __align__(16) float As[32 * 36];
    __shared__ __align__(16) float Bs[32 * 132];

    const float* __restrict__ h_prev = g_h[step & 1];
    float* __restrict__ h_next = g_h[(step & 1) ^ 1];

    const int tid = threadIdx.x;
    const int p0  = blockIdx.y * 32;
    const int jh0 = blockIdx.x * 32;
    const int ty = tid >> 5;        // 0..7   -> p micro-row base ty*4
    const int tx = tid & 31;        // 0..31  -> h column jh0+tx
    const int lr = tid >> 3;        // 0..31
    const int lc4 = (tid & 7) * 4;  // 0..28

    float acc[4][4] = {};  // [p][gate]

    for (int k0 = 0; k0 < H_DIM; k0 += 32) {
        {
            const float4 a = *(const float4*)(h_prev + (size_t)(p0 + lr) * H_DIM + k0 + lc4);
            As[(lc4 + 0) * 36 + lr] = a.x;
            As[(lc4 + 1) * 36 + lr] = a.y;
            As[(lc4 + 2) * 36 + lr] = a.z;
            As[(lc4 + 3) * 36 + lr] = a.w;
        }
        #pragma unroll
        for (int q = 0; q < 4; q++) {
            const int grow = q * H_DIM + jh0 + lr;
            const float4 b = *(const float4*)(W_hh + (size_t)grow * H_DIM + k0 + lc4);
            const int c = q * 32 + lr;
            Bs[(lc4 + 0) * 132 + c] = b.x;
            Bs[(lc4 + 1) * 132 + c] = b.y;
            Bs[(lc4 + 2) * 132 + c] = b.z;
            Bs[(lc4 + 3) * 132 + c] = b.w;
        }
        __syncthreads();
        #pragma unroll
        for (int k = 0; k < 32; k++) {
            const float4 a = *(const float4*)&As[k * 36 + ty * 4];
            const float b0 = Bs[k * 132 + tx];
            const float b1 = Bs[k * 132 + 32 + tx];
            const float b2 = Bs[k * 132 + 64 + tx];
            const float b3 = Bs[k * 132 + 96 + tx];
            const float av[4] = {a.x, a.y, a.z, a.w};
            #pragma unroll
            for (int i = 0; i < 4; i++) {
                acc[i][0] += av[i] * b0;
                acc[i][1] += av[i] * b1;
                acc[i][2] += av[i] * b2;
                acc[i][3] += av[i] * b3;
            }
        }
        __syncthreads();
    }

    const int jh = jh0 + tx;
    #pragma unroll
    for (int i = 0; i < 4; i++) {
        const int p = p0 + ty * 4 + i;
        const size_t xb = (size_t)(p * L_N + step) * G4 + jh;
        const float gi = acc[i][0] + g_xW[xb];
        const float gf = acc[i][1] + g_xW[xb + H_DIM];
        const float gg = acc[i][2] + g_xW[xb + 2 * H_DIM];
        const float go = acc[i][3] + g_xW[xb + 3 * H_DIM];
        const int ci = p * H_DIM + jh;
        const float c = sigm(gf) * g_c[ci] + sigm(gi) * tanhf(gg);
        g_c[ci] = c;
        const float hn = sigm(go) * tanhf(c);
        h_next[ci] = hn;
        if (lengths[p] - 1 == step) g_final[ci] = hn;
    }
}

// ---- generic projection: C[256,1024] = A @ W^T + bias ; sel picks A/C globals ----
__global__ void __launch_bounds__(256) gemm_proj(
    const float* __restrict__ W, const float* __restrict__ bias, const int sel)
{
    __shared__ __align__(16) float As[32 * 68];
    __shared__ __align__(16) float Bs[32 * 68];

    const float* __restrict__ A = (sel == 0) ? g_final : g_v;
    float* __restrict__ C = (sel == 0) ? g_v : g_attn;

    const int tid = threadIdx.x;
    const int m0 = blockIdx.y * 64;
    const int n0 = blockIdx.x * 64;
    const int ty = tid >> 4, tx = tid & 15;
    const int lr = tid >> 3;
    const int lc4 = (tid & 7) * 4;

    float acc[4][4] = {};

    for (int k0 = 0; k0 < H_DIM; k0 += 32) {
        #pragma unroll
        for (int h = 0; h < 2; h++) {
            const int r = lr + h * 32;
            const float4 a = *(const float4*)(A + (size_t)(m0 + r) * H_DIM + k0 + lc4);
            As[(lc4 + 0) * 68 + r] = a.x;
            As[(lc4 + 1) * 68 + r] = a.y;
            As[(lc4 + 2) * 68 + r] = a.z;
            As[(lc4 + 3) * 68 + r] = a.w;
            const float4 b = *(const float4*)(W + (size_t)(n0 + r) * H_DIM + k0 + lc4);
            Bs[(lc4 + 0) * 68 + r] = b.x;
            Bs[(lc4 + 1) * 68 + r] = b.y;
            Bs[(lc4 + 2) * 68 + r] = b.z;
            Bs[(lc4 + 3) * 68 + r] = b.w;
        }
        __syncthreads();
        #pragma unroll
        for (int k = 0; k < 32; k++) {
            const float4 a = *(const float4*)&As[k * 68 + ty * 4];
            const float4 b = *(const float4*)&Bs[k * 68 + tx * 4];
            const float av[4] = {a.x, a.y, a.z, a.w};
            const float bv[4] = {b.x, b.y, b.z, b.w};
            #pragma unroll
            for (int i = 0; i < 4; i++)
                #pragma unroll
                for (int j = 0; j < 4; j++)
                    acc[i][j] += av[i] * bv[j];
        }
        __syncthreads();
    }

    #pragma unroll
    for (int i = 0; i < 4; i++) {
        const int row = m0 + ty * 4 + i;
        #pragma unroll
        for (int j = 0; j < 4; j++) {
            const int col = n0 + tx * 4 + j;
            C[(size_t)row * H_DIM + col] = acc[i][j] + bias[col];
        }
    }
}

// ---- pooled[j] = max_p attn[p][j] ----
__global__ void colmax() {
    const int j = blockIdx.x * 256 + threadIdx.x;
    float m = -INFINITY;
    for (int p = 0; p < P_N; p++) m = fmaxf(m, g_attn[(size_t)p * H_DIM + j]);
    g_pooled[j] = m;
}

// ---- out[o] = sigmoid(pooled . W_lin[o] + b_lin[o]) ----
__global__ void final_k(const float* __restrict__ W_lin,
                        const float* __restrict__ b_lin, float* __restrict__ out)
{
    __shared__ float r0[256], r1[256];
    const int tid = threadIdx.x;
    float a0 = 0.0f, a1 = 0.0f;
    for (int j = tid; j < H_DIM; j += 256) {
        const float pv = g_pooled[j];
        a0 += pv * W_lin[j];
        a1 += pv * W_lin[H_DIM + j];
    }
    r0[tid] = a0; r1[tid] = a1;
    __syncthreads();
    for (int s = 128; s > 0; s >>= 1) {
        if (tid < s) { r0[tid] += r0[tid + s]; r1[tid] += r1[tid + s]; }
        __syncthreads();
    }
    if (tid == 0) {
        out[0] = sigm(r0[0] + b_lin[0]);
        out[1] = sigm(r1[0] + b_lin[1]);
    }
}

extern "C" void kernel_launch(void* const* d_in, const int* in_sizes, int n_in,
                              void* d_out, int out_size) {
    const int*   paths   = (const int*)d_in[0];
    const int*   lengths = (const int*)d_in[1];
    const float* emb     = (const float*)d_in[2];
    const float* W_ih    = (const float*)d_in[3];
    const float* W_hh    = (const float*)d_in[4];
    const float* b_ih    = (const float*)d_in[5];
    const float* b_hh    = (const float*)d_in[6];
    const float* W_in    = (const float*)d_in[7];
    const float* b_in    = (const float*)d_in[8];
    const float* W_out   = (const float*)d_in[9];
    const float* b_out   = (const float*)d_in[10];
    const float* W_lin   = (const float*)d_in[11];
    const float* b_lin   = (const float*)d_in[12];
    float* out = (float*)d_out;

    zero_hc<<<(P_N * H_DIM + 255) / 256, 256>>>();
    gemm_embed<<<dim3(G4 / 64, ROWS / 64), 256>>>(paths, emb, W_ih, b_ih, b_hh);
    for (int t = 0; t < L_N; t++)
        lstm_step<<<dim3(H_DIM / 32, P_N / 32), 256>>>(W_hh, lengths, t);
    // seq_len==1 attention: softmax == 1, ctx == v; q/k projections are dead code
    gemm_proj<<<dim3(H_DIM / 64, P_N / 64), 256>>>(W_in + (size_t)2 * H_DIM * H_DIM,
                                                   b_in + 2 * H_DIM, 0);
    gemm_proj<<<dim3(H_DIM / 64, P_N / 64), 256>>>(W_out, b_out, 1);
    colmax<<<H_DIM / 256, 256>>>();
    final_k<<<1, 256>>>(W_lin, b_lin, out);
}

// round 3
// speedup vs baseline: 2.1680x; 2.1680x over previous
#include <cuda_runtime.h>
#include <math.h>
#include <stdint.h>

#define P_N 256
#define L_N 64
#define I_DIM 512
#define H_DIM 1024
#define G4 4096
#define ROWS (P_N * L_N)  // 16384

// ---- scratch ----
__device__ float g_xW[(size_t)ROWS * G4];        // x@W_ih^T + b, permuted cols
__device__ float g_Whh_p[(size_t)G4 * H_DIM];    // permuted rows
__device__ float g_Wih_p[(size_t)G4 * I_DIM];    // permuted rows
__device__ float g_bias_p[G4];
__device__ float g_h[2][P_N * H_DIM];
__device__ float g_c[P_N * H_DIM];
__device__ float g_final[P_N * H_DIM];
__device__ float g_v[P_N * H_DIM];
__device__ float g_attn[P_N * H_DIM];
__device__ float g_pooled[H_DIM];

__device__ __forceinline__ float sigm(float x) { return 1.0f / (1.0f + expf(-x)); }

// m16n8k8 tf32 mma (sm_80+; no arch-specific 'a' features needed)
__device__ __forceinline__ void mma8(float* c, const uint32_t* a, const uint32_t* b) {
    asm volatile(
        "mma.sync.aligned.m16n8k8.row.col.f32.tf32.tf32.f32 "
        "{%0,%1,%2,%3}, {%4,%5,%6,%7}, {%8,%9}, {%0,%1,%2,%3};"
        : "+f"(c[0]), "+f"(c[1]), "+f"(c[2]), "+f"(c[3])
        : "r"(a[0]), "r"(a[1]), "r"(a[2]), "r"(a[3]), "r"(b[0]), "r"(b[1]));
}

// =================== small kernels ===================
__global__ void zero_hc() {
    int i = blockIdx.x * blockDim.x + threadIdx.x;
    if (i < P_N * H_DIM) { g_h[0][i] = 0.0f; g_c[i] = 0.0f; }
}

// permuted row r: q = (r>>3)&3, j = (r>>5)*8 + (r&7); orig row = q*H + j
__global__ void permute_weights(const float* __restrict__ Whh, const float* __restrict__ Wih,
                                const float* __restrict__ b_ih, const float* __restrict__ b_hh) {
    const int r = blockIdx.x;
    const int q = (r >> 3) & 3;
    const int j = (r >> 5) * 8 + (r & 7);
    const int orig = q * H_DIM + j;
    const float4* s1 = (const float4*)(Whh + (size_t)orig * H_DIM);
    float4* d1 = (float4*)(g_Whh_p + (size_t)r * H_DIM);
    for (int i = threadIdx.x; i < H_DIM / 4; i += blockDim.x) d1[i] = s1[i];
    const float4* s2 = (const float4*)(Wih + (size_t)orig * I_DIM);
    float4* d2 = (float4*)(g_Wih_p + (size_t)r * I_DIM);
    for (int i = threadIdx.x; i < I_DIM / 4; i += blockDim.x) d2[i] = s2[i];
    if (threadIdx.x == 0) g_bias_p[r] = b_ih[orig] + b_hh[orig];
}

// =================== embed GEMM: xW = gather(emb) @ Wih_p^T + bias_p ===================
// CTA 128x128, K=512 (16 chunks of 32). 256 thr = 8 warps (2m x 4n), warp tile 64x32.
#define E_SA 132
#define E_SB 132

__global__ void __launch_bounds__(256) gemm_embed_mma(
    const int* __restrict__ paths, const float* __restrict__ emb)
{
    __shared__ float As[32 * E_SA];   // [k][m]
    __shared__ float Bs[32 * E_SB];   // [k][n]
    __shared__ int toks[128];

    const int tid = threadIdx.x;
    const int lane = tid & 31, wid = tid >> 5;
    const int wm = wid >> 2, wn = wid & 3;     // 2 x 4 warps
    const int g = lane >> 2, tg = lane & 3;
    const int m0 = blockIdx.y * 128, n0 = blockIdx.x * 128;

    if (tid < 128) toks[tid] = paths[m0 + tid];
    __syncthreads();

    const int lrow = tid >> 3;       // 0..31
    const int lq = tid & 7;          // 0..7 -> k offset lq*4

    float cfr[4][4][4];
    #pragma unroll
    for (int a = 0; a < 4; a++)
        #pragma unroll
        for (int b = 0; b < 4; b++)
            #pragma unroll
            for (int c = 0; c < 4; c++) cfr[a][b][c] = 0.0f;

    float4 sa[4], sb[4];
    // prefetch chunk 0
    #pragma unroll
    for (int i = 0; i < 4; i++) {
        const int row = lrow + i * 32;
        sa[i] = *(const float4*)(emb + (size_t)toks[row] * I_DIM + lq * 4);
        sb[i] = *(const float4*)(g_Wih_p + (size_t)(n0 + row) * I_DIM + lq * 4);
    }

    for (int ch = 0; ch < 16; ch++) {
        // store staged chunk to smem (transposed [k][row])
        #pragma unroll
        for (int i = 0; i < 4; i++) {
            const int row = lrow + i * 32;
            As[(lq * 4 + 0) * E_SA + row] = sa[i].x;
            As[(lq * 4 + 1) * E_SA + row] = sa[i].y;
            As[(lq * 4 + 2) * E_SA + row] = sa[i].z;
            As[(lq * 4 + 3) * E_SA + row] = sa[i].w;
            Bs[(lq * 4 + 0) * E_SB + row] = sb[i].x;
            Bs[(lq * 4 + 1) * E_SB + row] = sb[i].y;
            Bs[(lq * 4 + 2) * E_SB + row] = sb[i].z;
            Bs[(lq * 4 + 3) * E_SB + row] = sb[i].w;
        }
        __syncthreads();
        if (ch < 15) {
            const int k0 = (ch + 1) * 32;
            #pragma unroll
            for (int i = 0; i < 4; i++) {
                const int row = lrow + i * 32;
                sa[i] = *(const float4*)(emb + (size_t)toks[row] * I_DIM + k0 + lq * 4);
                sb[i] = *(const float4*)(g_Wih_p + (size_t)(n0 + row) * I_DIM + k0 + lq * 4);
            }
        }
        #pragma unroll
        for (int ks = 0; ks < 4; ks++) {
            const int kk = ks * 8;
            uint32_t af[4][4], bf[4][2];
            #pragma unroll
            for (int mf = 0; mf < 4; mf++) {
                const int mb = wm * 64 + mf * 16 + g;
                af[mf][0] = __float_as_uint(As[(kk + tg) * E_SA + mb]);
                af[mf][1] = __float_as_uint(As[(kk + tg) * E_SA + mb + 8]);
                af[mf][2] = __float_as_uint(As[(kk + tg + 4) * E_SA + mb]);
                af[mf][3] = __float_as_uint(As[(kk + tg + 4) * E_SA + mb + 8]);
            }
            #pragma unroll
            for (int nf = 0; nf < 4; nf++) {
                const int nb = wn * 32 + nf * 8 + g;
                bf[nf][0] = __float_as_uint(Bs[(kk + tg) * E_SB + nb]);
                bf[nf][1] = __float_as_uint(Bs[(kk + tg + 4) * E_SB + nb]);
            }
            #pragma unroll
            for (int mf = 0; mf < 4; mf++)
                #pragma unroll
                for (int nf = 0; nf < 4; nf++)
                    mma8(cfr[mf][nf], af[mf], bf[nf]);
        }
        __syncthreads();
    }

    // epilogue: write permuted-col xW + bias
    const int colw = n0 + wn * 32;
    #pragma unroll
    for (int mf = 0; mf < 4; mf++) {
        #pragma unroll
        for (int rr = 0; rr < 2; rr++) {
            const int row = m0 + wm * 64 + mf * 16 + g + rr * 8;
            float* orow = g_xW + (size_t)row * G4 + colw;
            #pragma unroll
            for (int q = 0; q < 4; q++) {
                const int cl = q * 8 + 2 * tg;
                const float2 bv = *(const float2*)&g_bias_p[colw + cl];
                float2 v;
                v.x = cfr[mf][q][rr * 2 + 0] + bv.x;
                v.y = cfr[mf][q][rr * 2 + 1] + bv.y;
                *(float2*)(orow + cl) = v;
            }
        }
    }
}

// =================== LSTM step: gates = h_prev @ Whh_p^T (+xW), fused update ===================
// CTA 64x128, K=1024 (32 chunks). 256 thr = 8 warps (2m x 4n), warp tile 32x32.
#define L_SA 68
#define L_SB 132

__global__ void __launch_bounds__(256) lstm_step_mma(
    const int* __restrict__ lengths, const int step)
{
    __shared__ float As[32 * L_SA];   // [k][m], m=64
    __shared__ float Bs[32 * L_SB];   // [k][n], n=128

    const float* __restrict__ h_prev = g_h[step & 1];
    float* __restrict__ h_next = g_h[(step & 1) ^ 1];

    const int tid = threadIdx.x;
    const int lane = tid & 31, wid = tid >> 5;
    const int wm = wid >> 2, wn = wid & 3;
    const int g = lane >> 2, tg = lane & 3;
    const int m0 = blockIdx.y * 64, n0 = blockIdx.x * 128;

    const int lrow = tid >> 3;
    const int lq = tid & 7;

    float cfr[2][4][4];
    #pragma unroll
    for (int a = 0; a < 2; a++)
        #pragma unroll
        for (int b = 0; b < 4; b++)
            #pragma unroll
            for (int c = 0; c < 4; c++) cfr[a][b][c] = 0.0f;

    float4 sa[2], sb[4];
    #pragma unroll
    for (int i = 0; i < 2; i++)
        sa[i] = *(const float4*)(h_prev + (size_t)(m0 + lrow + i * 32) * H_DIM + lq * 4);
    #pragma unroll
    for (int i = 0; i < 4; i++)
        sb[i] = *(const float4*)(g_Whh_p + (size_t)(n0 + lrow + i * 32) * H_DIM + lq * 4);

    for (int ch = 0; ch < 32; ch++) {
        #pragma unroll
        for (int i = 0; i < 2; i++) {
            const int row = lrow + i * 32;
            As[(lq * 4 + 0) * L_SA + row] = sa[i].x;
            As[(lq * 4 + 1) * L_SA + row] = sa[i].y;
            As[(lq * 4 + 2) * L_SA + row] = sa[i].z;
            As[(lq * 4 + 3) * L_SA + row] = sa[i].w;
        }
        #pragma unroll
        for (int i = 0; i < 4; i++) {
            const int row = lrow + i * 32;
            Bs[(lq * 4 + 0) * L_SB + row] = sb[i].x;
            Bs[(lq * 4 + 1) * L_SB + row] = sb[i].y;
            Bs[(lq * 4 + 2) * L_SB + row] = sb[i].z;
            Bs[(lq * 4 + 3) * L_SB + row] = sb[i].w;
        }
        __syncthreads();
        if (ch < 31) {
            const int k0 = (ch + 1) * 32;
            #pragma unroll
            for (int i = 0; i < 2; i++)
                sa[i] = *(const float4*)(h_prev + (size_t)(m0 + lrow + i * 32) * H_DIM + k0 + lq * 4);
            #pragma unroll
            for (int i = 0; i < 4; i++)
                sb[i] = *(const float4*)(g_Whh_p + (size_t)(n0 + lrow + i * 32) * H_DIM + k0 + lq * 4);
        }
        #pragma unroll
        for (int ks = 0; ks < 4; ks++) {
            const int kk = ks * 8;
            uint32_t af[2][4], bf[4][2];
            #pragma unroll
            for (int mf = 0; mf < 2; mf++) {
                const int mb = wm * 32 + mf * 16 + g;
                af[mf][0] = __float_as_uint(As[(kk + tg) * L_SA + mb]);
                af[mf][1] = __float_as_uint(As[(kk + tg) * L_SA + mb + 8]);
                af[mf][2] = __float_as_uint(As[(kk + tg + 4) * L_SA + mb]);
                af[mf][3] = __float_as_uint(As[(kk + tg + 4) * L_SA + mb + 8]);
            }
            #pragma unroll
            for (int nf = 0; nf < 4; nf++) {
                const int nb = wn * 32 + nf * 8 + g;
                bf[nf][0] = __float_as_uint(Bs[(kk + tg) * L_SB + nb]);
                bf[nf][1] = __float_as_uint(Bs[(kk + tg + 4) * L_SB + nb]);
            }
            #pragma unroll
            for (int mf = 0; mf < 2; mf++)
                #pragma unroll
                for (int nf = 0; nf < 4; nf++)
                    mma8(cfr[mf][nf], af[mf], bf[nf]);
        }
        __syncthreads();
    }

    // epilogue: nfrag q = gate q; thread cols {2tg, 2tg+1} = same j pair for all gates
    const int colw = n0 + wn * 32;
    const int jpair = (colw >> 5) * 8 + 2 * tg;   // h-column of jj=0
    #pragma unroll
    for (int mf = 0; mf < 2; mf++) {
        #pragma unroll
        for (int rr = 0; rr < 2; rr++) {
            const int p = m0 + wm * 32 + mf * 16 + g + rr * 8;
            const size_t xb = (size_t)(p * L_N + step) * G4 + colw;
            float2 xw[4];
            #pragma unroll
            for (int q = 0; q < 4; q++)
                xw[q] = *(const float2*)&g_xW[xb + q * 8 + 2 * tg];
            const int ci = p * H_DIM + jpair;
            const float2 cold = *(const float2*)&g_c[ci];

            const float gi0 = cfr[mf][0][rr * 2 + 0] + xw[0].x;
            const float gf0 = cfr[mf][1][rr * 2 + 0] + xw[1].x;
            const float gg0 = cfr[mf][2][rr * 2 + 0] + xw[2].x;
            const float go0 = cfr[mf][3][rr * 2 + 0] + xw[3].x;
            const float gi1 = cfr[mf][0][rr * 2 + 1] + xw[0].y;
            const float gf1 = cfr[mf][1][rr * 2 + 1] + xw[1].y;
            const float gg1 = cfr[mf][2][rr * 2 + 1] + xw[2].y;
            const float go1 = cfr[mf][3][rr * 2 + 1] + xw[3].y;

            float2 cv, hv;
            cv.x = sigm(gf0) * cold.x + sigm(gi0) * tanhf(gg0);
            cv.y = sigm(gf1) * cold.y + sigm(gi1) * tanhf(gg1);
            hv.x = sigm(go0) * tanhf(cv.x);
            hv.y = sigm(go1) * tanhf(cv.y);

            *(float2*)&g_c[ci] = cv;
            *(float2*)&h_next[ci] = hv;
            if (lengths[p] - 1 == step) *(float2*)&g_final[ci] = hv;
        }
    }
}

// =================== tail (SIMT, small) ===================
__global__ void __launch_bounds__(256) gemm_proj(
    const float* __restrict__ W, const float* __restrict__ bias, const int sel)
{
    __shared__ __align__(16) float As[32 * 68];
    __shared__ __align__(16) float Bs[32 * 68];
    const float* __restrict__ A = (sel == 0) ? g_final : g_v;
    float* __restrict__ C = (sel == 0) ? g_v : g_attn;
    const int tid = threadIdx.x;
    const int m0 = blockIdx.y * 64, n0 = blockIdx.x * 64;
    const int ty = tid >> 4, tx = tid & 15;
    const int lr = tid >> 3, lc4 = (tid & 7) * 4;
    float acc[4][4] = {};
    for (int k0 = 0; k0 < H_DIM; k0 += 32) {
        #pragma unroll
        for (int h = 0; h < 2; h++) {
            const int r = lr + h * 32;
            const float4 a = *(const float4*)(A + (size_t)(m0 + r) * H_DIM + k0 + lc4);
            As[(lc4 + 0) * 68 + r] = a.x; As[(lc4 + 1) * 68 + r] = a.y;
            As[(lc4 + 2) * 68 + r] = a.z; As[(lc4 + 3) * 68 + r] = a.w;
            const float4 b = *(const float4*)(W + (size_t)(n0 + r) * H_DIM + k0 + lc4);
            Bs[(lc4 + 0) * 68 + r] = b.x; Bs[(lc4 + 1) * 68 + r] = b.y;
            Bs[(lc4 + 2) * 68 + r] = b.z; Bs[(lc4 + 3) * 68 + r] = b.w;
        }
        __syncthreads();
        #pragma unroll
        for (int k = 0; k < 32; k++) {
            const float4 a = *(const float4*)&As[k * 68 + ty * 4];
            const float4 b = *(const float4*)&Bs[k * 68 + tx * 4];
            const float av[4] = {a.x, a.y, a.z, a.w};
            const float bv[4] = {b.x, b.y, b.z, b.w};
            #pragma unroll
            for (int i = 0; i < 4; i++)
                #pragma unroll
                for (int j = 0; j < 4; j++)
                    acc[i][j] += av[i] * bv[j];
        }
        __syncthreads();
    }
    #pragma unroll
    for (int i = 0; i < 4; i++) {
        const int row = m0 + ty * 4 + i;
        #pragma unroll
        for (int j = 0; j < 4; j++)
            C[(size_t)row * H_DIM + n0 + tx * 4 + j] = acc[i][j] + bias[n0 + tx * 4 + j];
    }
}

__global__ void colmax() {
    const int j = blockIdx.x * 256 + threadIdx.x;
    float m = -INFINITY;
    for (int p = 0; p < P_N; p++) m = fmaxf(m, g_attn[(size_t)p * H_DIM + j]);
    g_pooled[j] = m;
}

__global__ void final_k(const float* __restrict__ W_lin,
                        const float* __restrict__ b_lin, float* __restrict__ out)
{
    __shared__ float r0[256], r1[256];
    const int tid = threadIdx.x;
    float a0 = 0.0f, a1 = 0.0f;
    for (int j = tid; j < H_DIM; j += 256) {
        const float pv = g_pooled[j];
        a0 += pv * W_lin[j];
        a1 += pv * W_lin[H_DIM + j];
    }
    r0[tid] = a0; r1[tid] = a1;
    __syncthreads();
    for (int s = 128; s > 0; s >>= 1) {
        if (tid < s) { r0[tid] += r0[tid + s]; r1[tid] += r1[tid + s]; }
        __syncthreads();
    }
    if (tid == 0) {
        out[0] = sigm(r0[0] + b_lin[0]);
        out[1] = sigm(r1[0] + b_lin[1]);
    }
}

extern "C" void kernel_launch(void* const* d_in, const int* in_sizes, int n_in,
                              void* d_out, int out_size) {
    const int*   paths   = (const int*)d_in[0];
    const int*   lengths = (const int*)d_in[1];
    const float* emb     = (const float*)d_in[2];
    const float* W_ih    = (const float*)d_in[3];
    const float* W_hh    = (const float*)d_in[4];
    const float* b_ih    = (const float*)d_in[5];
    const float* b_hh    = (const float*)d_in[6];
    const float* W_in    = (const float*)d_in[7];
    const float* b_in    = (const float*)d_in[8];
    const float* W_out   = (const float*)d_in[9];
    const float* b_out   = (const float*)d_in[10];
    const float* W_lin   = (const float*)d_in[11];
    const float* b_lin   = (const float*)d_in[12];
    float* out = (float*)d_out;

    permute_weights<<<G4, 128>>>(W_hh, W_ih, b_ih, b_hh);
    zero_hc<<<(P_N * H_DIM + 255) / 256, 256>>>();
    gemm_embed_mma<<<dim3(G4 / 128, ROWS / 128), 256>>>(paths, emb);
    for (int t = 0; t < L_N; t++)
        lstm_step_mma<<<dim3(G4 / 128, P_N / 64), 256>>>(lengths, t);
    // seq_len==1 attention: softmax == 1, ctx == v; q/k projections are dead code
    gemm_proj<<<dim3(H_DIM / 64, P_N / 64), 256>>>(W_in + (size_t)2 * H_DIM * H_DIM,
                                                   b_in + 2 * H_DIM, 0);
    gemm_proj<<<dim3(H_DIM / 64, P_N / 64), 256>>>(W_out, b_out, 1);
    colmax<<<H_DIM / 256, 256>>>();
    final_k<<<1, 256>>>(W_lin, b_lin, out);
}

// round 4
// speedup vs baseline: 5.5077x; 2.5405x over previous
#include <cuda_runtime.h>
#include <cuda_bf16.h>
#include <math.h>
#include <stdint.h>

#define P_N 256
#define L_N 64
#define I_DIM 512
#define H_DIM 1024
#define G4 4096
#define ROWS (P_N * L_N)  // 16384

// ---- scratch ----
__device__ float g_xW[(size_t)ROWS * G4];                       // permuted cols, fp32
__device__ __align__(128) __nv_bfloat16 g_x[(size_t)ROWS * I_DIM];      // gathered emb, bf16
__device__ __align__(128) __nv_bfloat16 g_Whh_b[(size_t)G4 * H_DIM];    // permuted rows, bf16
__device__ __align__(128) __nv_bfloat16 g_Wih_b[(size_t)G4 * I_DIM];    // permuted rows, bf16
__device__ float g_bias_p[G4];
__device__ __align__(128) __nv_bfloat16 g_hb[2][P_N * H_DIM];   // hidden, bf16 (MMA A operand)
__device__ float g_c[P_N * H_DIM];
__device__ float g_final[P_N * H_DIM];
__device__ float g_v[P_N * H_DIM];
__device__ float g_attn[P_N * H_DIM];
__device__ float g_pooled[H_DIM];

__device__ __forceinline__ float sigm(float x) { return 1.0f / (1.0f + expf(-x)); }

__device__ __forceinline__ uint32_t smem_u32(const void* p) {
    uint32_t a;
    asm("{ .reg .u64 t; cvta.to.shared.u64 t, %1; cvt.u32.u64 %0, t; }" : "=r"(a) : "l"(p));
    return a;
}
// 128B rows, 16B segs, XOR swizzle -> conflict-free stores + ldmatrix
__device__ __forceinline__ uint32_t swz(uint32_t base, int row, int seg) {
    return base + (uint32_t)row * 128u + (uint32_t)((seg ^ (row & 7)) << 4);
}
__device__ __forceinline__ void cpa16(uint32_t dst, const void* src) {
    asm volatile("cp.async.ca.shared.global [%0], [%1], 16;" :: "r"(dst), "l"(src) : "memory");
}
#define CP_COMMIT() asm volatile("cp.async.commit_group;" ::: "memory")
#define CP_WAIT(n)  asm volatile("cp.async.wait_group " #n ";" ::: "memory")
#define LDM_X4(r0, r1, r2, r3, a)                                                       \
    asm volatile("ldmatrix.sync.aligned.m8n8.x4.shared.b16 {%0,%1,%2,%3}, [%4];"        \
                 : "=r"(r0), "=r"(r1), "=r"(r2), "=r"(r3) : "r"(a))

__device__ __forceinline__ void mmabf(float* c, const uint32_t* a, const uint32_t* b) {
    asm volatile(
        "mma.sync.aligned.m16n8k16.row.col.f32.bf16.bf16.f32 "
        "{%0,%1,%2,%3}, {%4,%5,%6,%7}, {%8,%9}, {%0,%1,%2,%3};"
        : "+f"(c[0]), "+f"(c[1]), "+f"(c[2]), "+f"(c[3])
        : "r"(a[0]), "r"(a[1]), "r"(a[2]), "r"(a[3]), "r"(b[0]), "r"(b[1]));
}

// =================== prep kernels ===================
__global__ void zero_hc() {
    int i = blockIdx.x * blockDim.x + threadIdx.x;
    if (i < P_N * H_DIM) {
        g_hb[0][i] = __float2bfloat16(0.0f);
        g_c[i] = 0.0f;
    }
}

// permuted row r: q = (r>>3)&3, j = (r>>5)*8 + (r&7); orig row = q*H + j. bf16 convert.
__global__ void permute_weights(const float* __restrict__ Whh, const float* __restrict__ Wih,
                                const float* __restrict__ b_ih, const float* __restrict__ b_hh) {
    const int r = blockIdx.x;
    const int q = (r >> 3) & 3;
    const int j = (r >> 5) * 8 + (r & 7);
    const int orig = q * H_DIM + j;
    const float4* s1 = (const float4*)(Whh + (size_t)orig * H_DIM);
    __nv_bfloat162* d1 = (__nv_bfloat162*)(g_Whh_b + (size_t)r * H_DIM);
    for (int i = threadIdx.x; i < H_DIM / 4; i += blockDim.x) {
        const float4 v = s1[i];
        d1[i * 2 + 0] = __floats2bfloat162_rn(v.x, v.y);
        d1[i * 2 + 1] = __floats2bfloat162_rn(v.z, v.w);
    }
    const float4* s2 = (const float4*)(Wih + (size_t)orig * I_DIM);
    __nv_bfloat162* d2 = (__nv_bfloat162*)(g_Wih_b + (size_t)r * I_DIM);
    for (int i = threadIdx.x; i < I_DIM / 4; i += blockDim.x) {
        const float4 v = s2[i];
        d2[i * 2 + 0] = __floats2bfloat162_rn(v.x, v.y);
        d2[i * 2 + 1] = __floats2bfloat162_rn(v.z, v.w);
    }
    if (threadIdx.x == 0) g_bias_p[r] = b_ih[orig] + b_hh[orig];
}

// gather + convert: g_x[row] = bf16(emb[paths_flat[row]])
__global__ void gather_emb(const int* __restrict__ paths, const float* __restrict__ emb) {
    const int row = blockIdx.x * 2 + (threadIdx.x >> 7);
    const int k4 = (threadIdx.x & 127) * 4;
    const int tok = paths[row];
    const float4 v = *(const float4*)(emb + (size_t)tok * I_DIM + k4);
    __nv_bfloat162* d = (__nv_bfloat162*)(g_x + (size_t)row * I_DIM + k4);
    d[0] = __floats2bfloat162_rn(v.x, v.y);
    d[1] = __floats2bfloat162_rn(v.z, v.w);
}

// =================== embed GEMM (bf16): xW = g_x @ Wih_b^T + bias ===================
// CTA 128x128, K=512 (8 chunks of 64). 8 warps 2m x 4n, warp 64x32. 4-stage cp.async.
#define E_STG 32768  // A 16KB + B 16KB

__global__ void __launch_bounds__(256) gemm_embed_bf(int dummy) {
    extern __shared__ char sm[];
    const uint32_t sb = smem_u32(sm);
    const int tid = threadIdx.x;
    const int lane = tid & 31, wid = tid >> 5;
    const int wm = wid >> 2, wn = wid & 3;
    const int gr = lane >> 2, tg = lane & 3;
    const int m0 = blockIdx.y * 128, n0 = blockIdx.x * 128;

    const __nv_bfloat16* A_g = g_x;
    const __nv_bfloat16* B_g = g_Wih_b;

    // ldmatrix address precompute (per-lane constants except seg/mfrag)
    const int a_row_l = (lane & 7) + ((lane >> 3) & 1) * 8;  // + mfrag*16 + wm*64
    const int a_seg_l = lane >> 4;                           // + 2*s
    const int b_row_l = wn * 32 + (lane & 7) + (lane >> 4) * 8;  // + half*16
    const int b_seg_l = (lane >> 3) & 1;                     // + 2*s

    float cfr[4][4][4];
    #pragma unroll
    for (int a = 0; a < 4; a++)
        #pragma unroll
        for (int b = 0; b < 4; b++)
            #pragma unroll
            for (int c = 0; c < 4; c++) cfr[a][b][c] = 0.0f;

    #define E_ISSUE(ch, st) do {                                                        \
        const uint32_t ab = sb + (st) * E_STG;                                          \
        const uint32_t bb = ab + 16384;                                                 \
        const int k0 = (ch) * 64;                                                       \
        _Pragma("unroll")                                                               \
        for (int i = 0; i < 4; i++) {                                                   \
            const int idx = tid + i * 256;                                              \
            const int row = idx >> 3, seg = idx & 7;                                    \
            cpa16(swz(ab, row, seg), A_g + (size_t)(m0 + row) * I_DIM + k0 + seg * 8);  \
            cpa16(swz(bb, row, seg), B_g + (size_t)(n0 + row) * I_DIM + k0 + seg * 8);  \
        }                                                                               \
        CP_COMMIT();                                                                    \
    } while (0)

    E_ISSUE(0, 0); E_ISSUE(1, 1); E_ISSUE(2, 2);

    for (int ch = 0; ch < 8; ch++) {
        if (ch < 6) CP_WAIT(2);
        else if (ch == 6) CP_WAIT(1);
        else CP_WAIT(0);
        __syncthreads();
        if (ch + 3 < 8) E_ISSUE(ch + 3, (ch + 3) & 3);

        const uint32_t ab = sb + (ch & 3) * E_STG;
        const uint32_t bb = ab + 16384;
        #pragma unroll
        for (int s = 0; s < 4; s++) {
            uint32_t af[4][4], bf[4][2];
            #pragma unroll
            for (int mf = 0; mf < 4; mf++)
                LDM_X4(af[mf][0], af[mf][1], af[mf][2], af[mf][3],
                       swz(ab, wm * 64 + mf * 16 + a_row_l, 2 * s + a_seg_l));
            #pragma unroll
            for (int h = 0; h < 2; h++)
                LDM_X4(bf[2 * h][0], bf[2 * h][1], bf[2 * h + 1][0], bf[2 * h + 1][1],
                       swz(bb, b_row_l + h * 16, 2 * s + b_seg_l));
            #pragma unroll
            for (int mf = 0; mf < 4; mf++)
                #pragma unroll
                for (int nf = 0; nf < 4; nf++)
                    mmabf(cfr[mf][nf], af[mf], bf[nf]);
        }
    }

    const int colw = n0 + wn * 32;
    #pragma unroll
    for (int mf = 0; mf < 4; mf++) {
        #pragma unroll
        for (int rr = 0; rr < 2; rr++) {
            const int row = m0 + wm * 64 + mf * 16 + gr + rr * 8;
            float* orow = g_xW + (size_t)row * G4 + colw;
            #pragma unroll
            for (int q = 0; q < 4; q++) {
                const int cl = q * 8 + 2 * tg;
                const float2 bv = *(const float2*)&g_bias_p[colw + cl];
                float2 v;
                v.x = cfr[mf][q][rr * 2 + 0] + bv.x;
                v.y = cfr[mf][q][rr * 2 + 1] + bv.y;
                *(float2*)(orow + cl) = v;
            }
        }
    }
    #undef E_ISSUE
}

// =================== LSTM step (bf16): gates = h_prev @ Whh_b^T + xW, fused update ===================
// CTA 64x128, K=1024 (16 chunks of 64). 8 warps 2m x 4n, warp 32x32. 4-stage cp.async.
#define L_STG 24576  // A 8KB + B 16KB

__global__ void __launch_bounds__(256) lstm_step_bf(const int* __restrict__ lengths, const int step) {
    extern __shared__ char sm[];
    const uint32_t sb = smem_u32(sm);
    const int tid = threadIdx.x;
    const int lane = tid & 31, wid = tid >> 5;
    const int wm = wid >> 2, wn = wid & 3;
    const int gr = lane >> 2, tg = lane & 3;
    const int m0 = blockIdx.y * 64, n0 = blockIdx.x * 128;

    const __nv_bfloat16* __restrict__ A_g = g_hb[step & 1];
    __nv_bfloat16* __restrict__ h_next = g_hb[(step & 1) ^ 1];

    const int a_row_l = (lane & 7) + ((lane >> 3) & 1) * 8;
    const int a_seg_l = lane >> 4;
    const int b_row_l = wn * 32 + (lane & 7) + (lane >> 4) * 8;
    const int b_seg_l = (lane >> 3) & 1;

    float cfr[2][4][4];
    #pragma unroll
    for (int a = 0; a < 2; a++)
        #pragma unroll
        for (int b = 0; b < 4; b++)
            #pragma unroll
            for (int c = 0; c < 4; c++) cfr[a][b][c] = 0.0f;

    #define L_ISSUE(ch, st) do {                                                        \
        const uint32_t ab = sb + (st) * L_STG;                                          \
        const uint32_t bb = ab + 8192;                                                  \
        const int k0 = (ch) * 64;                                                       \
        _Pragma("unroll")                                                               \
        for (int i = 0; i < 2; i++) {                                                   \
            const int idx = tid + i * 256;                                              \
            const int row = idx >> 3, seg = idx & 7;                                    \
            cpa16(swz(ab, row, seg), A_g + (size_t)(m0 + row) * H_DIM + k0 + seg * 8);  \
        }                                                                               \
        _Pragma("unroll")                                                               \
        for (int i = 0; i < 4; i++) {                                                   \
            const int idx = tid + i * 256;                                              \
            const int row = idx >> 3, seg = idx & 7;                                    \
            cpa16(swz(bb, row, seg),                                                    \
                  g_Whh_b + (size_t)(n0 + row) * H_DIM + k0 + seg * 8);                 \
        }                                                                               \
        CP_COMMIT();                                                                    \
    } while (0)

    L_ISSUE(0, 0); L_ISSUE(1, 1); L_ISSUE(2, 2);

    for (int ch = 0; ch < 16; ch++) {
        if (ch < 14) CP_WAIT(2);
        else if (ch == 14) CP_WAIT(1);
        else CP_WAIT(0);
        __syncthreads();
        if (ch + 3 < 16) L_ISSUE(ch + 3, (ch + 3) & 3);

        const uint32_t ab = sb + (ch & 3) * L_STG;
        const uint32_t bb = ab + 8192;
        #pragma unroll
        for (int s = 0; s < 4; s++) {
            uint32_t af[2][4], bf[4][2];
            #pragma unroll
            for (int mf = 0; mf < 2; mf++)
                LDM_X4(af[mf][0], af[mf][1], af[mf][2], af[mf][3],
                       swz(ab, wm * 32 + mf * 16 + a_row_l, 2 * s + a_seg_l));
            #pragma unroll
            for (int h = 0; h < 2; h++)
                LDM_X4(bf[2 * h][0], bf[2 * h][1], bf[2 * h + 1][0], bf[2 * h + 1][1],
                       swz(bb, b_row_l + h * 16, 2 * s + b_seg_l));
            #pragma unroll
            for (int mf = 0; mf < 2; mf++)
                #pragma unroll
                for (int nf = 0; nf < 4; nf++)
                    mmabf(cfr[mf][nf], af[mf], bf[nf]);
        }
    }

    // epilogue: nfrag q = gate q; thread cols {2tg,2tg+1} = h-col pair j, j+1
    const int colw = n0 + wn * 32;
    const int jpair = (colw >> 5) * 8 + 2 * tg;
    #pragma unroll
    for (int mf = 0; mf < 2; mf++) {
        #pragma unroll
        for (int rr = 0; rr < 2; rr++) {
            const int p = m0 + wm * 32 + mf * 16 + gr + rr * 8;
            const size_t xb = (size_t)(p * L_N + step) * G4 + colw;
            float2 xw[4];
            #pragma unroll
            for (int q = 0; q < 4; q++)
                xw[q] = *(const float2*)&g_xW[xb + q * 8 + 2 * tg];
            const int ci = p * H_DIM + jpair;
            const float2 cold = *(const float2*)&g_c[ci];

            const float gi0 = cfr[mf][0][rr * 2 + 0] + xw[0].x;
            const float gf0 = cfr[mf][1][rr * 2 + 0] + xw[1].x;
            const float gg0 = cfr[mf][2][rr * 2 + 0] + xw[2].x;
            const float go0 = cfr[mf][3][rr * 2 + 0] + xw[3].x;
            const float gi1 = cfr[mf][0][rr * 2 + 1] + xw[0].y;
            const float gf1 = cfr[mf][1][rr * 2 + 1] + xw[1].y;
            const float gg1 = cfr[mf][2][rr * 2 + 1] + xw[2].y;
            const float go1 = cfr[mf][3][rr * 2 + 1] + xw[3].y;

            float2 cv, hv;
            cv.x = sigm(gf0) * cold.x + sigm(gi0) * tanhf(gg0);
            cv.y = sigm(gf1) * cold.y + sigm(gi1) * tanhf(gg1);
            hv.x = sigm(go0) * tanhf(cv.x);
            hv.y = sigm(go1) * tanhf(cv.y);

            *(float2*)&g_c[ci] = cv;
            *(__nv_bfloat162*)&h_next[ci] = __floats2bfloat162_rn(hv.x, hv.y);
            if (lengths[p] - 1 == step) *(float2*)&g_final[ci] = hv;
        }
    }
    #undef L_ISSUE
}

// =================== tail (SIMT, small) ===================
__global__ void __launch_bounds__(256) gemm_proj(
    const float* __restrict__ W, const float* __restrict__ bias, const int sel)
{
    __shared__ __align__(16) float As[32 * 68];
    __shared__ __align__(16) float Bs[32 * 68];
    const float* __restrict__ A = (sel == 0) ? g_final : g_v;
    float* __restrict__ C = (sel == 0) ? g_v : g_attn;
    const int tid = threadIdx.x;
    const int m0 = blockIdx.y * 64, n0 = blockIdx.x * 64;
    const int ty = tid >> 4, tx = tid & 15;
    const int lr = tid >> 3, lc4 = (tid & 7) * 4;
    float acc[4][4] = {};
    for (int k0 = 0; k0 < H_DIM; k0 += 32) {
        #pragma unroll
        for (int h = 0; h < 2; h++) {
            const int r = lr + h * 32;
            const float4 a = *(const float4*)(A + (size_t)(m0 + r) * H_DIM + k0 + lc4);
            As[(lc4 + 0) * 68 + r] = a.x; As[(lc4 + 1) * 68 + r] = a.y;
            As[(lc4 + 2) * 68 + r] = a.z; As[(lc4 + 3) * 68 + r] = a.w;
            const float4 b = *(const float4*)(W + (size_t)(n0 + r) * H_DIM + k0 + lc4);
            Bs[(lc4 + 0) * 68 + r] = b.x; Bs[(lc4 + 1) * 68 + r] = b.y;
            Bs[(lc4 + 2) * 68 + r] = b.z; Bs[(lc4 + 3) * 68 + r] = b.w;
        }
        __syncthreads();
        #pragma unroll
        for (int k = 0; k < 32; k++) {
            const float4 a = *(const float4*)&As[k * 68 + ty * 4];
            const float4 b = *(const float4*)&Bs[k * 68 + tx * 4];
            const float av[4] = {a.x, a.y, a.z, a.w};
            const float bv[4] = {b.x, b.y, b.z, b.w};
            #pragma unroll
            for (int i = 0; i < 4; i++)
                #pragma unroll
                for (int j = 0; j < 4; j++)
                    acc[i][j] += av[i] * bv[j];
        }
        __syncthreads();
    }
    #pragma unroll
    for (int i = 0; i < 4; i++) {
        const int row = m0 + ty * 4 + i;
        #pragma unroll
        for (int j = 0; j < 4; j++)
            C[(size_t)row * H_DIM + n0 + tx * 4 + j] = acc[i][j] + bias[n0 + tx * 4 + j];
    }
}

__global__ void colmax() {
    const int j = blockIdx.x * 256 + threadIdx.x;
    float m = -INFINITY;
    for (int p = 0; p < P_N; p++) m = fmaxf(m, g_attn[(size_t)p * H_DIM + j]);
    g_pooled[j] = m;
}

__global__ void final_k(const float* __restrict__ W_lin,
                        const float* __restrict__ b_lin, float* __restrict__ out)
{
    __shared__ float r0[256], r1[256];
    const int tid = threadIdx.x;
    float a0 = 0.0f, a1 = 0.0f;
    for (int j = tid; j < H_DIM; j += 256) {
        const float pv = g_pooled[j];
        a0 += pv * W_lin[j];
        a1 += pv * W_lin[H_DIM + j];
    }
    r0[tid] = a0; r1[tid] = a1;
    __syncthreads();
    for (int s = 128; s > 0; s >>= 1) {
        if (tid < s) { r0[tid] += r0[tid + s]; r1[tid] += r1[tid + s]; }
        __syncthreads();
    }
    if (tid == 0) {
        out[0] = sigm(r0[0] + b_lin[0]);
        out[1] = sigm(r1[0] + b_lin[1]);
    }
}

extern "C" void kernel_launch(void* const* d_in, const int* in_sizes, int n_in,
                              void* d_out, int out_size) {
    const int*   paths   = (const int*)d_in[0];
    const int*   lengths = (const int*)d_in[1];
    const float* emb     = (const float*)d_in[2];
    const float* W_ih    = (const float*)d_in[3];
    const float* W_hh    = (const float*)d_in[4];
    const float* b_ih    = (const float*)d_in[5];
    const float* b_hh    = (const float*)d_in[6];
    const float* W_in    = (const float*)d_in[7];
    const float* b_in    = (const float*)d_in[8];
    const float* W_out   = (const float*)d_in[9];
    const float* b_out   = (const float*)d_in[10];
    const float* W_lin   = (const float*)d_in[11];
    const float* b_lin   = (const float*)d_in[12];
    float* out = (float*)d_out;

    static int attr_done = 0;
    if (!attr_done) {
        cudaFuncSetAttribute(gemm_embed_bf, cudaFuncAttributeMaxDynamicSharedMemorySize, 4 * E_STG);
        cudaFuncSetAttribute(lstm_step_bf,  cudaFuncAttributeMaxDynamicSharedMemorySize, 4 * L_STG);
        attr_done = 1;
    }

    permute_weights<<<G4, 128>>>(W_hh, W_ih, b_ih, b_hh);
    gather_emb<<<ROWS / 2, 256>>>(paths, emb);
    zero_hc<<<(P_N * H_DIM + 255) / 256, 256>>>();
    gemm_embed_bf<<<dim3(G4 / 128, ROWS / 128), 256, 4 * E_STG>>>(0);
    for (int t = 0; t < L_N; t++)
        lstm_step_bf<<<dim3(G4 / 128, P_N / 64), 256, 4 * L_STG>>>(lengths, t);
    // seq_len==1 attention: softmax == 1, ctx == v; q/k projections are dead code
    gemm_proj<<<dim3(H_DIM / 64, P_N / 64), 256>>>(W_in + (size_t)2 * H_DIM * H_DIM,
                                                   b_in + 2 * H_DIM, 0);
    gemm_proj<<<dim3(H_DIM / 64, P_N / 64), 256>>>(W_out, b_out, 1);
    colmax<<<H_DIM / 256, 256>>>();
    final_k<<<1, 256>>>(W_lin, b_lin, out);
}